// round 16
// baseline (speedup 1.0000x reference)
#include <cuda_runtime.h>
#include <cuda_fp16.h>

#define NN 100000
#define EE 3200000
#define ETOT (EE + NN)
#define AGG_GRID 1184
#define HB ((ETOT + 255) / 256)
#define NB ((NN + 1023) / 1024)
#define FULLM 0xffffffffu

// ---- device scratch ----
__device__ __half2 g_hA[NN * 32];
__device__ __half2 g_hC[NN * 32];
__device__ float2  g_asc1[NN], g_adc1[NN];
__device__ float2  g_asc2[NN], g_adc2[NN];
__device__ float   g_asc3[NN], g_adc3[NN];
__device__ float4  g_h3[NN];
__device__ int     g_cnt[NN];          // zero-init; scan re-zeroes after read
__device__ int     g_cur[NN];
__device__ int2    g_pk1[ETOT];        // {src, half2(ex0,ex1)}
__device__ int     g_aggr[NB];

__device__ __forceinline__ __half2 H2(unsigned u) { return *(__half2*)&u; }
__device__ __forceinline__ unsigned U32(__half2 h) { return *(unsigned*)&h; }

// ---- fast exp on FMA/ALU pipes ----
__device__ __forceinline__ float fast_exp(float x) {
    float y = x * 1.4426950408889634f;
    float n = rintf(y);
    float t = (y - n) * 0.6931471805599453f;
    float p = 1.0f + t * (1.0f + t * (0.5f + t * (0.16666667f +
              t * (0.041666667f + t * 0.0083333338f))));
    int ni = (int)n;
    return p * __int_as_float((ni + 127) << 23);
}

__device__ int g_rowptr[NN + 1];

// ==================== CSR build (+ fused gemm1) ====================

__global__ void __launch_bounds__(256) k_hist_gemm1(const int* __restrict__ ei,
                                                    const float* __restrict__ x,
                                                    const float* __restrict__ W,
                                                    const float* __restrict__ as_,
                                                    const float* __restrict__ ad_) {
    __shared__ float Ws[640];
    if (blockIdx.x < HB) {
        if (blockIdx.x == 0 && threadIdx.x < NB) g_aggr[threadIdx.x] = 0;
        int i = blockIdx.x * 256 + threadIdx.x;
        if (i >= ETOT) return;
        int dst = (i < EE) ? ei[EE + i] : (i - EE);
        atomicAdd(&g_cnt[dst], 1);
        return;
    }
    int t = threadIdx.x;
    for (int i = t; i < 640; i += 256) Ws[i] = W[i];
    __syncthreads();
    int lane = t & 31, w = t >> 5;
    int bid = blockIdx.x - HB;
    int warpsTotal = (gridDim.x - HB) * 8;
    float vas0 = as_[2 * lane], vas1 = as_[2 * lane + 1];
    float vad0 = ad_[2 * lane], vad1 = ad_[2 * lane + 1];
    for (int node = bid * 8 + w; node < NN; node += warpsTotal) {
        float a0 = 0.f, a1 = 0.f;
        #pragma unroll
        for (int k = 0; k < 10; k++) {
            float xv = x[node * 10 + k];
            a0 = fmaf(xv, Ws[k * 64 + 2 * lane], a0);
            a1 = fmaf(xv, Ws[k * 64 + 2 * lane + 1], a1);
        }
        g_hA[node * 32 + lane] = __floats2half2_rn(a0, a1);
        float ps = a0 * vas0 + a1 * vas1;
        float pd = a0 * vad0 + a1 * vad1;
        #pragma unroll
        for (int o = 8; o >= 1; o >>= 1) {
            ps += __shfl_xor_sync(FULLM, ps, o);
            pd += __shfl_xor_sync(FULLM, pd, o);
        }
        float ps1 = __shfl_sync(FULLM, ps, 16);
        float pd1 = __shfl_sync(FULLM, pd, 16);
        if (lane == 0) {
            g_asc1[node] = make_float2(ps, ps1);
            g_adc1[node] = make_float2(pd, pd1);
        }
    }
}

// single-kernel scan with parallel lookback
__global__ void __launch_bounds__(1024) k_scan() {
    __shared__ int sd[1024];
    __shared__ int s_off;
    int b = blockIdx.x, t = threadIdx.x;
    int i = b * 1024 + t;
    int v = 0;
    if (i < NN) { v = g_cnt[i]; g_cnt[i] = 0; }
    sd[t] = v;
    __syncthreads();
    #pragma unroll
    for (int o = 1; o < 1024; o <<= 1) {
        int a = (t >= o) ? sd[t - o] : 0;
        __syncthreads();
        sd[t] += a;
        __syncthreads();
    }
    int incl = sd[t];
    int total = sd[1023];
    if (t == 0) atomicExch(&g_aggr[b], total + 1);
    if (t < 32) {
        int acc = 0;
        for (int j = t; j < b; j += 32) {
            int val;
            do { val = *(volatile int*)&g_aggr[j]; } while (val == 0);
            acc += val - 1;
        }
        #pragma unroll
        for (int o = 16; o >= 1; o >>= 1) acc += __shfl_xor_sync(FULLM, acc, o);
        if (t == 0) s_off = acc;
    }
    __syncthreads();
    if (i < NN) {
        int rp = incl - v + s_off;
        g_rowptr[i] = rp;
        g_cur[i]    = rp;
    }
    if (b == gridDim.x - 1 && t == 1023) g_rowptr[NN] = s_off + total;
}

// scatter + layer-1 edge exp
__global__ void k_scatter_ex(const int* __restrict__ ei) {
    int i = blockIdx.x * blockDim.x + threadIdx.x;
    if (i >= ETOT) return;
    int src, dst;
    if (i < EE) { src = ei[i]; dst = ei[EE + i]; }
    else        { src = i - EE; dst = i - EE; }
    int pos = atomicAdd(&g_cur[dst], 1);
    float2 as = g_asc1[src];
    float2 ad = g_adc1[dst];
    float e0 = as.x + ad.x; e0 = (e0 > 0.f) ? e0 : 0.2f * e0;
    float e1 = as.y + ad.y; e1 = (e1 > 0.f) ? e1 : 0.2f * e1;
    __half2 ex = __floats2half2_rn(fast_exp(e0), fast_exp(e1));
    g_pk1[pos] = make_int2(src, *(int*)&ex);
}

// ==== consume: pre-splatted {src, ex_head} per lane-head, HFMA2 ====

__device__ __forceinline__ void consume_splat(const __half2* __restrict__ feat,
                                              const int2* __restrict__ myPk,
                                              int cnt, int lane,
                                              float& a0, float& a1) {
    int nb8 = (cnt + 7) >> 3;
    for (int jb = 0; jb < nb8; jb++) {
        int base = jb * 8;
        __half2 acch = __float2half2_rn(0.f);
        #pragma unroll
        for (int u = 0; u < 8; u++) {
            int2 q = myPk[base + u];
            acch = __hfma2(H2(q.y), feat[q.x * 32 + lane], acch);
        }
        float2 af = __half22float2(acch);
        a0 += af.x;
        a1 += af.y;
    }
}

// layer-1 agg: coalesced packed load, PRMT dual-splat staging
__device__ __forceinline__ void agg_node_pk(const __half2* __restrict__ feat,
                                            int2* __restrict__ s_lo,
                                            int2* __restrict__ s_hi,
                                            int beg, int end,
                                            int head, int lane,
                                            float& a0, float& a1, float& zout) {
    const int2* myPk = head ? s_hi : s_lo;
    float z0 = 0.f, z1 = 0.f;
    a0 = 0.f; a1 = 0.f;
    for (int cb = beg; cb < end; cb += 32) {
        int cnt = min(32, end - cb);
        int2 p = make_int2(0, 0);
        if (lane < cnt) p = g_pk1[cb + lane];
        unsigned exu = (unsigned)p.y;
        s_lo[lane] = make_int2(p.x, (int)__byte_perm(exu, exu, 0x1010u));
        s_hi[lane] = make_int2(p.x, (int)__byte_perm(exu, exu, 0x3232u));
        float2 ef = __half22float2(H2(exu));
        z0 += ef.x; z1 += ef.y;
        __syncwarp();
        consume_splat(feat, myPk, cnt, lane, a0, a1);
        __syncwarp();
    }
    #pragma unroll
    for (int o = 16; o >= 1; o >>= 1) {
        z0 += __shfl_xor_sync(FULLM, z0, o);
        z1 += __shfl_xor_sync(FULLM, z1, o);
    }
    zout = head ? z1 : z0;
}

// layer-2 agg: ex from asc2/adc2, dual-splat staging
__device__ __forceinline__ void agg_node_l2(const __half2* __restrict__ feat,
                                            int2* __restrict__ s_lo,
                                            int2* __restrict__ s_hi,
                                            float2 ad, int beg, int end,
                                            int head, int lane,
                                            float& a0, float& a1, float& zout) {
    const int2* myPk = head ? s_hi : s_lo;
    float z0 = 0.f, z1 = 0.f;
    a0 = 0.f; a1 = 0.f;
    for (int cb = beg; cb < end; cb += 32) {
        int cnt = min(32, end - cb);
        int s = 0;
        float ex0 = 0.f, ex1 = 0.f;
        if (lane < cnt) {
            s = g_pk1[cb + lane].x;
            float2 as = g_asc2[s];
            float e0 = as.x + ad.x; e0 = (e0 > 0.f) ? e0 : 0.2f * e0;
            float e1 = as.y + ad.y; e1 = (e1 > 0.f) ? e1 : 0.2f * e1;
            ex0 = fast_exp(e0); ex1 = fast_exp(e1);
            z0 += ex0; z1 += ex1;
        }
        s_lo[lane] = make_int2(s, (int)U32(__float2half2_rn(ex0)));
        s_hi[lane] = make_int2(s, (int)U32(__float2half2_rn(ex1)));
        __syncwarp();
        consume_splat(feat, myPk, cnt, lane, a0, a1);
        __syncwarp();
    }
    #pragma unroll
    for (int o = 16; o >= 1; o >>= 1) {
        z0 += __shfl_xor_sync(FULLM, z0, o);
        z1 += __shfl_xor_sync(FULLM, z1, o);
    }
    zout = head ? z1 : z0;
}

// ============ fused: aggregate layer1 + GEMM layer2 (fp16 W) ========

__global__ void __launch_bounds__(256, 8) k_aggmm2(const float* __restrict__ bias,
                                                   const float* __restrict__ W,
                                                   const float* __restrict__ as_,
                                                   const float* __restrict__ ad_) {
    __shared__ __half2 Wh[64][32];     // Wh[k][l] = {W[k][2l], W[k][2l+1]}
    __shared__ int2    s_lo[8][32];
    __shared__ int2    s_hi[8][32];
    __shared__ __half2 xs[8][64];      // xs[w][k] = {x_k, x_k} splat
    int t = threadIdx.x;
    for (int idx = t; idx < 2048; idx += 256) {
        int k = idx >> 5, l = idx & 31;
        Wh[k][l] = __floats2half2_rn(W[k * 64 + 2 * l], W[k * 64 + 2 * l + 1]);
    }
    __syncthreads();
    int lane = t & 31, w = t >> 5;
    int head = lane >> 4;
    int warpsTotal = gridDim.x * 8;
    float vb0 = bias[2 * lane], vb1 = bias[2 * lane + 1];
    float vas0 = as_[2 * lane], vas1 = as_[2 * lane + 1];
    float vad0 = ad_[2 * lane], vad1 = ad_[2 * lane + 1];

    for (int node = blockIdx.x * 8 + w; node < NN; node += warpsTotal) {
        int beg = g_rowptr[node], end = g_rowptr[node + 1];
        float a0, a1, z;
        agg_node_pk(g_hA, s_lo[w], s_hi[w], beg, end, head, lane, a0, a1, z);
        float rz = 1.f / z;
        float r0 = fmaxf(a0 * rz + vb0, 0.f);
        float r1 = fmaxf(a1 * rz + vb1, 0.f);
        xs[w][2 * lane]     = __float2half2_rn(r0);
        xs[w][2 * lane + 1] = __float2half2_rn(r1);
        __syncwarp();
        float o0 = 0.f, o1 = 0.f;
        #pragma unroll
        for (int kb = 0; kb < 64; kb += 8) {
            __half2 acch = __float2half2_rn(0.f);
            #pragma unroll
            for (int u = 0; u < 8; u++) {
                acch = __hfma2(xs[w][kb + u], Wh[kb + u][lane], acch);
            }
            float2 af = __half22float2(acch);
            o0 += af.x;
            o1 += af.y;
        }
        g_hC[node * 32 + lane] = __floats2half2_rn(o0, o1);
        float ps = o0 * vas0 + o1 * vas1;
        float pd = o0 * vad0 + o1 * vad1;
        #pragma unroll
        for (int o = 8; o >= 1; o >>= 1) {
            ps += __shfl_xor_sync(FULLM, ps, o);
            pd += __shfl_xor_sync(FULLM, pd, o);
        }
        float ps1 = __shfl_sync(FULLM, ps, 16);
        float pd1 = __shfl_sync(FULLM, pd, 16);
        if (lane == 0) {
            g_asc2[node] = make_float2(ps, ps1);
            g_adc2[node] = make_float2(pd, pd1);
        }
        __syncwarp();
    }
}

// ============ fused: aggregate layer2 + GEMM layer3 ================

__global__ void __launch_bounds__(256, 8) k_aggmm3(const float* __restrict__ bias,
                                                   const float* __restrict__ W,
                                                   const float* __restrict__ as_,
                                                   const float* __restrict__ ad_) {
    __shared__ int2 s_lo[8][32];
    __shared__ int2 s_hi[8][32];
    int t = threadIdx.x;
    int lane = t & 31, w = t >> 5;
    int head = lane >> 4;
    int warpsTotal = gridDim.x * 8;
    float4 w0 = ((const float4*)W)[2 * lane];
    float4 w1 = ((const float4*)W)[2 * lane + 1];
    float as0 = as_[0], as1 = as_[1], as2 = as_[2], as3 = as_[3];
    float ad0 = ad_[0], ad1 = ad_[1], ad2 = ad_[2], ad3 = ad_[3];
    float vb0 = bias[2 * lane], vb1 = bias[2 * lane + 1];

    for (int node = blockIdx.x * 8 + w; node < NN; node += warpsTotal) {
        int beg = g_rowptr[node], end = g_rowptr[node + 1];
        float2 ad = g_adc2[node];
        float a0, a1, z;
        agg_node_l2(g_hC, s_lo[w], s_hi[w], ad, beg, end, head, lane, a0, a1, z);
        float rz = 1.f / z;
        float r0 = fmaxf(a0 * rz + vb0, 0.f);
        float r1 = fmaxf(a1 * rz + vb1, 0.f);
        float4 acc;
        acc.x = r0 * w0.x + r1 * w1.x;
        acc.y = r0 * w0.y + r1 * w1.y;
        acc.z = r0 * w0.z + r1 * w1.z;
        acc.w = r0 * w0.w + r1 * w1.w;
        #pragma unroll
        for (int o = 16; o >= 1; o >>= 1) {
            acc.x += __shfl_xor_sync(FULLM, acc.x, o);
            acc.y += __shfl_xor_sync(FULLM, acc.y, o);
            acc.z += __shfl_xor_sync(FULLM, acc.z, o);
            acc.w += __shfl_xor_sync(FULLM, acc.w, o);
        }
        if (lane == 0) {
            g_h3[node] = acc;
            g_asc3[node] = acc.x * as0 + acc.y * as1 + acc.z * as2 + acc.w * as3;
            g_adc3[node] = acc.x * ad0 + acc.y * ad1 + acc.z * ad2 + acc.w * ad3;
        }
    }
}

// ===================== layer-3 aggregation + output ================

__global__ void __launch_bounds__(256) k_agg4(const float* __restrict__ bias,
                                              float4* __restrict__ out) {
    int t = threadIdx.x;
    int lane = t & 31, w = t >> 5;
    int warpsTotal = gridDim.x * 8;
    for (int node = blockIdx.x * 8 + w; node < NN; node += warpsTotal) {
        int beg = g_rowptr[node], end = g_rowptr[node + 1];
        float ad = g_adc3[node];
        float z = 0.f;
        float4 acc = make_float4(0.f, 0.f, 0.f, 0.f);
        #pragma unroll 4
        for (int i = beg + lane; i < end; i += 32) {
            int s = g_pk1[i].x;
            float e = g_asc3[s] + ad;
            e = (e > 0.f) ? e : 0.2f * e;
            float ex = fast_exp(e);
            z += ex;
            float4 hv = g_h3[s];
            acc.x = fmaf(ex, hv.x, acc.x);
            acc.y = fmaf(ex, hv.y, acc.y);
            acc.z = fmaf(ex, hv.z, acc.z);
            acc.w = fmaf(ex, hv.w, acc.w);
        }
        #pragma unroll
        for (int o = 16; o >= 1; o >>= 1) {
            z     += __shfl_xor_sync(FULLM, z, o);
            acc.x += __shfl_xor_sync(FULLM, acc.x, o);
            acc.y += __shfl_xor_sync(FULLM, acc.y, o);
            acc.z += __shfl_xor_sync(FULLM, acc.z, o);
            acc.w += __shfl_xor_sync(FULLM, acc.w, o);
        }
        if (lane == 0) {
            float4 o4;
            o4.x = 100.f / (1.f + __expf(-(acc.x / z + bias[0])));
            o4.y = 100.f / (1.f + __expf(-(acc.y / z + bias[1])));
            o4.z = 100.f / (1.f + __expf(-(acc.z / z + bias[2])));
            o4.w = 100.f / (1.f + __expf(-(acc.w / z + bias[3])));
            out[node] = o4;
        }
    }
}

// ============================== launch =============================

extern "C" void kernel_launch(void* const* d_in, const int* in_sizes, int n_in,
                              void* d_out, int out_size) {
    const float* x   = (const float*)d_in[0];
    const int*   ei  = (const int*)d_in[1];
    const float* W1  = (const float*)d_in[2];
    const float* a1s = (const float*)d_in[3];
    const float* a1d = (const float*)d_in[4];
    const float* b1  = (const float*)d_in[5];
    const float* W2  = (const float*)d_in[6];
    const float* a2s = (const float*)d_in[7];
    const float* a2d = (const float*)d_in[8];
    const float* b2  = (const float*)d_in[9];
    const float* W3  = (const float*)d_in[10];
    const float* a3s = (const float*)d_in[11];
    const float* a3d = (const float*)d_in[12];
    const float* b3  = (const float*)d_in[13];
    float4* out = (float4*)d_out;

    k_hist_gemm1<<<HB + AGG_GRID, 256>>>(ei, x, W1, a1s, a1d);
    k_scan<<<NB, 1024>>>();
    k_scatter_ex<<<(ETOT + 255) / 256, 256>>>(ei);
    k_aggmm2<<<AGG_GRID, 256>>>(b1, W2, a2s, a2d);     // profiled slot
    k_aggmm3<<<AGG_GRID, 256>>>(b2, W3, a3s, a3d);
    k_agg4<<<AGG_GRID, 256>>>(b3, out);
}

// round 17
// speedup vs baseline: 1.0492x; 1.0492x over previous
#include <cuda_runtime.h>
#include <cuda_fp16.h>

#define NN 100000
#define EE 3200000
#define ETOT (EE + NN)
#define AGG_GRID 1184
#define HB ((ETOT + 255) / 256)
#define NB ((NN + 1023) / 1024)
#define FULLM 0xffffffffu

struct __align__(32) N3 { float4 h; float asc; float pad0, pad1, pad2; };

// ---- device scratch ----
__device__ __half2 g_hA[NN * 32];
__device__ __half2 g_hC[NN * 32];
__device__ float2  g_asc1[NN], g_adc1[NN];
__device__ float2  g_asc2[NN], g_adc2[NN];
__device__ float   g_adc3[NN];
__device__ N3      g_n3[NN];           // packed layer-3 {features, asc}
__device__ int     g_cnt[NN];          // zero-init; scan re-zeroes after read
__device__ int     g_cur[NN];
__device__ int2    g_pk1[ETOT];        // {src, half2(ex0,ex1)}
__device__ int     g_aggr[NB];

__device__ __forceinline__ __half2 H2(unsigned u) { return *(__half2*)&u; }
__device__ __forceinline__ unsigned U32(__half2 h) { return *(unsigned*)&h; }

// ---- fast exp on FMA/ALU pipes ----
__device__ __forceinline__ float fast_exp(float x) {
    float y = x * 1.4426950408889634f;
    float n = rintf(y);
    float t = (y - n) * 0.6931471805599453f;
    float p = 1.0f + t * (1.0f + t * (0.5f + t * (0.16666667f +
              t * (0.041666667f + t * 0.0083333338f))));
    int ni = (int)n;
    return p * __int_as_float((ni + 127) << 23);
}

__device__ int g_rowptr[NN + 1];

// ==================== CSR build (+ fused gemm1) ====================

__global__ void __launch_bounds__(256) k_hist_gemm1(const int* __restrict__ ei,
                                                    const float* __restrict__ x,
                                                    const float* __restrict__ W,
                                                    const float* __restrict__ as_,
                                                    const float* __restrict__ ad_) {
    __shared__ float Ws[640];
    if (blockIdx.x < HB) {
        if (blockIdx.x == 0 && threadIdx.x < NB) g_aggr[threadIdx.x] = 0;
        int i = blockIdx.x * 256 + threadIdx.x;
        if (i >= ETOT) return;
        int dst = (i < EE) ? ei[EE + i] : (i - EE);
        atomicAdd(&g_cnt[dst], 1);
        return;
    }
    int t = threadIdx.x;
    for (int i = t; i < 640; i += 256) Ws[i] = W[i];
    __syncthreads();
    int lane = t & 31, w = t >> 5;
    int bid = blockIdx.x - HB;
    int warpsTotal = (gridDim.x - HB) * 8;
    float vas0 = as_[2 * lane], vas1 = as_[2 * lane + 1];
    float vad0 = ad_[2 * lane], vad1 = ad_[2 * lane + 1];
    for (int node = bid * 8 + w; node < NN; node += warpsTotal) {
        float a0 = 0.f, a1 = 0.f;
        #pragma unroll
        for (int k = 0; k < 10; k++) {
            float xv = x[node * 10 + k];
            a0 = fmaf(xv, Ws[k * 64 + 2 * lane], a0);
            a1 = fmaf(xv, Ws[k * 64 + 2 * lane + 1], a1);
        }
        g_hA[node * 32 + lane] = __floats2half2_rn(a0, a1);
        float ps = a0 * vas0 + a1 * vas1;
        float pd = a0 * vad0 + a1 * vad1;
        #pragma unroll
        for (int o = 8; o >= 1; o >>= 1) {
            ps += __shfl_xor_sync(FULLM, ps, o);
            pd += __shfl_xor_sync(FULLM, pd, o);
        }
        float ps1 = __shfl_sync(FULLM, ps, 16);
        float pd1 = __shfl_sync(FULLM, pd, 16);
        if (lane == 0) {
            g_asc1[node] = make_float2(ps, ps1);
            g_adc1[node] = make_float2(pd, pd1);
        }
    }
}

// single-kernel scan with parallel lookback
__global__ void __launch_bounds__(1024) k_scan() {
    __shared__ int sd[1024];
    __shared__ int s_off;
    int b = blockIdx.x, t = threadIdx.x;
    int i = b * 1024 + t;
    int v = 0;
    if (i < NN) { v = g_cnt[i]; g_cnt[i] = 0; }
    sd[t] = v;
    __syncthreads();
    #pragma unroll
    for (int o = 1; o < 1024; o <<= 1) {
        int a = (t >= o) ? sd[t - o] : 0;
        __syncthreads();
        sd[t] += a;
        __syncthreads();
    }
    int incl = sd[t];
    int total = sd[1023];
    if (t == 0) atomicExch(&g_aggr[b], total + 1);
    if (t < 32) {
        int acc = 0;
        for (int j = t; j < b; j += 32) {
            int val;
            do { val = *(volatile int*)&g_aggr[j]; } while (val == 0);
            acc += val - 1;
        }
        #pragma unroll
        for (int o = 16; o >= 1; o >>= 1) acc += __shfl_xor_sync(FULLM, acc, o);
        if (t == 0) s_off = acc;
    }
    __syncthreads();
    if (i < NN) {
        int rp = incl - v + s_off;
        g_rowptr[i] = rp;
        g_cur[i]    = rp;
    }
    if (b == gridDim.x - 1 && t == 1023) g_rowptr[NN] = s_off + total;
}

// scatter + layer-1 edge exp
__global__ void k_scatter_ex(const int* __restrict__ ei) {
    int i = blockIdx.x * blockDim.x + threadIdx.x;
    if (i >= ETOT) return;
    int src, dst;
    if (i < EE) { src = ei[i]; dst = ei[EE + i]; }
    else        { src = i - EE; dst = i - EE; }
    int pos = atomicAdd(&g_cur[dst], 1);
    float2 as = g_asc1[src];
    float2 ad = g_adc1[dst];
    float e0 = as.x + ad.x; e0 = (e0 > 0.f) ? e0 : 0.2f * e0;
    float e1 = as.y + ad.y; e1 = (e1 > 0.f) ? e1 : 0.2f * e1;
    __half2 ex = __floats2half2_rn(fast_exp(e0), fast_exp(e1));
    g_pk1[pos] = make_int2(src, *(int*)&ex);
}

// ==== consume variant A (aggmm2): per-edge head-select, low regs ====

__device__ __forceinline__ void consume_sel(const __half2* __restrict__ feat,
                                            const int2* __restrict__ s_pk,
                                            int cnt, int head, int lane,
                                            float& a0, float& a1) {
    int nb8 = (cnt + 7) >> 3;
    for (int jb = 0; jb < nb8; jb++) {
        int base = jb * 8;
        __half2 acch = __float2half2_rn(0.f);
        #pragma unroll
        for (int u = 0; u < 8; u++) {
            int2 q = s_pk[base + u];
            __half2 eh = *(__half2*)&q.y;
            __half2 es = head ? __high2half2(eh) : __low2half2(eh);
            acch = __hfma2(es, feat[q.x * 32 + lane], acch);
        }
        float2 af = __half22float2(acch);
        a0 += af.x;
        a1 += af.y;
    }
}

// ==== consume variant B (aggmm3): pre-splatted per-head arrays ======

__device__ __forceinline__ void consume_splat(const __half2* __restrict__ feat,
                                              const int2* __restrict__ myPk,
                                              int cnt, int lane,
                                              float& a0, float& a1) {
    int nb8 = (cnt + 7) >> 3;
    for (int jb = 0; jb < nb8; jb++) {
        int base = jb * 8;
        __half2 acch = __float2half2_rn(0.f);
        #pragma unroll
        for (int u = 0; u < 8; u++) {
            int2 q = myPk[base + u];
            acch = __hfma2(H2(q.y), feat[q.x * 32 + lane], acch);
        }
        float2 af = __half22float2(acch);
        a0 += af.x;
        a1 += af.y;
    }
}

// layer-1 agg (aggmm2): single staging, select in consume
__device__ __forceinline__ void agg_node_pk(const __half2* __restrict__ feat,
                                            int2* __restrict__ s_pk,
                                            int beg, int end,
                                            int head, int lane,
                                            float& a0, float& a1, float& zout) {
    float z0 = 0.f, z1 = 0.f;
    a0 = 0.f; a1 = 0.f;
    for (int cb = beg; cb < end; cb += 32) {
        int cnt = min(32, end - cb);
        int2 p = make_int2(0, 0);
        if (lane < cnt) p = g_pk1[cb + lane];
        s_pk[lane] = p;
        float2 ef = __half22float2(*(__half2*)&p.y);
        z0 += ef.x; z1 += ef.y;
        __syncwarp();
        consume_sel(feat, s_pk, cnt, head, lane, a0, a1);
        __syncwarp();
    }
    #pragma unroll
    for (int o = 16; o >= 1; o >>= 1) {
        z0 += __shfl_xor_sync(FULLM, z0, o);
        z1 += __shfl_xor_sync(FULLM, z1, o);
    }
    zout = head ? z1 : z0;
}

// layer-2 agg (aggmm3): ex from asc2/adc2, dual-splat staging
__device__ __forceinline__ void agg_node_l2(const __half2* __restrict__ feat,
                                            int2* __restrict__ s_lo,
                                            int2* __restrict__ s_hi,
                                            float2 ad, int beg, int end,
                                            int head, int lane,
                                            float& a0, float& a1, float& zout) {
    const int2* myPk = head ? s_hi : s_lo;
    float z0 = 0.f, z1 = 0.f;
    a0 = 0.f; a1 = 0.f;
    for (int cb = beg; cb < end; cb += 32) {
        int cnt = min(32, end - cb);
        int s = 0;
        float ex0 = 0.f, ex1 = 0.f;
        if (lane < cnt) {
            s = g_pk1[cb + lane].x;
            float2 as = g_asc2[s];
            float e0 = as.x + ad.x; e0 = (e0 > 0.f) ? e0 : 0.2f * e0;
            float e1 = as.y + ad.y; e1 = (e1 > 0.f) ? e1 : 0.2f * e1;
            ex0 = fast_exp(e0); ex1 = fast_exp(e1);
            z0 += ex0; z1 += ex1;
        }
        s_lo[lane] = make_int2(s, (int)U32(__float2half2_rn(ex0)));
        s_hi[lane] = make_int2(s, (int)U32(__float2half2_rn(ex1)));
        __syncwarp();
        consume_splat(feat, myPk, cnt, lane, a0, a1);
        __syncwarp();
    }
    #pragma unroll
    for (int o = 16; o >= 1; o >>= 1) {
        z0 += __shfl_xor_sync(FULLM, z0, o);
        z1 += __shfl_xor_sync(FULLM, z1, o);
    }
    zout = head ? z1 : z0;
}

// ===== fused: aggregate layer1 + GEMM layer2 (fp16 W, paired LDS.64) =====

__global__ void __launch_bounds__(256) k_aggmm2(const float* __restrict__ bias,
                                                const float* __restrict__ W,
                                                const float* __restrict__ as_,
                                                const float* __restrict__ ad_) {
    // Whp[kb][l] = {half2(W[2kb][2l],W[2kb][2l+1]), half2(W[2kb+1][2l],W[2kb+1][2l+1])}
    __shared__ __align__(8) uint2   Whp[32][32];
    __shared__ int2    s_pk[8][32];
    __shared__ __align__(8) __half2 xs[8][64];   // xs[w][k] = {x_k, x_k}
    int t = threadIdx.x;
    for (int idx = t; idx < 1024; idx += 256) {
        int kb = idx >> 5, l = idx & 31;
        __half2 h0 = __floats2half2_rn(W[(2 * kb) * 64 + 2 * l],     W[(2 * kb) * 64 + 2 * l + 1]);
        __half2 h1 = __floats2half2_rn(W[(2 * kb + 1) * 64 + 2 * l], W[(2 * kb + 1) * 64 + 2 * l + 1]);
        Whp[kb][l] = make_uint2(U32(h0), U32(h1));
    }
    __syncthreads();
    int lane = t & 31, w = t >> 5;
    int head = lane >> 4;
    int warpsTotal = gridDim.x * 8;
    float vb0 = bias[2 * lane], vb1 = bias[2 * lane + 1];
    float vas0 = as_[2 * lane], vas1 = as_[2 * lane + 1];
    float vad0 = ad_[2 * lane], vad1 = ad_[2 * lane + 1];
    const uint2* xq = (const uint2*)&xs[w][0];

    for (int node = blockIdx.x * 8 + w; node < NN; node += warpsTotal) {
        int beg = g_rowptr[node], end = g_rowptr[node + 1];
        float a0, a1, z;
        agg_node_pk(g_hA, s_pk[w], beg, end, head, lane, a0, a1, z);
        float rz = 1.f / z;
        float r0 = fmaxf(a0 * rz + vb0, 0.f);
        float r1 = fmaxf(a1 * rz + vb1, 0.f);
        xs[w][2 * lane]     = __float2half2_rn(r0);
        xs[w][2 * lane + 1] = __float2half2_rn(r1);
        __syncwarp();
        float o0 = 0.f, o1 = 0.f;
        #pragma unroll
        for (int kq = 0; kq < 32; kq += 4) {       // 8 k-steps per flush
            __half2 acch = __float2half2_rn(0.f);
            #pragma unroll
            for (int u = 0; u < 4; u++) {
                uint2 xv = xq[kq + u];
                uint2 wv = Whp[kq + u][lane];
                acch = __hfma2(H2(xv.x), H2(wv.x), acch);
                acch = __hfma2(H2(xv.y), H2(wv.y), acch);
            }
            float2 af = __half22float2(acch);
            o0 += af.x;
            o1 += af.y;
        }
        g_hC[node * 32 + lane] = __floats2half2_rn(o0, o1);
        float ps = o0 * vas0 + o1 * vas1;
        float pd = o0 * vad0 + o1 * vad1;
        #pragma unroll
        for (int o = 8; o >= 1; o >>= 1) {
            ps += __shfl_xor_sync(FULLM, ps, o);
            pd += __shfl_xor_sync(FULLM, pd, o);
        }
        float ps1 = __shfl_sync(FULLM, ps, 16);
        float pd1 = __shfl_sync(FULLM, pd, 16);
        if (lane == 0) {
            g_asc2[node] = make_float2(ps, ps1);
            g_adc2[node] = make_float2(pd, pd1);
        }
        __syncwarp();
    }
}

// ============ fused: aggregate layer2 + GEMM layer3 ================

__global__ void __launch_bounds__(256) k_aggmm3(const float* __restrict__ bias,
                                                const float* __restrict__ W,
                                                const float* __restrict__ as_,
                                                const float* __restrict__ ad_) {
    __shared__ int2 s_lo[8][32];
    __shared__ int2 s_hi[8][32];
    int t = threadIdx.x;
    int lane = t & 31, w = t >> 5;
    int head = lane >> 4;
    int warpsTotal = gridDim.x * 8;
    float4 w0 = ((const float4*)W)[2 * lane];
    float4 w1 = ((const float4*)W)[2 * lane + 1];
    float as0 = as_[0], as1 = as_[1], as2 = as_[2], as3 = as_[3];
    float ad0 = ad_[0], ad1 = ad_[1], ad2 = ad_[2], ad3 = ad_[3];
    float vb0 = bias[2 * lane], vb1 = bias[2 * lane + 1];

    for (int node = blockIdx.x * 8 + w; node < NN; node += warpsTotal) {
        int beg = g_rowptr[node], end = g_rowptr[node + 1];
        float2 ad = g_adc2[node];
        float a0, a1, z;
        agg_node_l2(g_hC, s_lo[w], s_hi[w], ad, beg, end, head, lane, a0, a1, z);
        float rz = 1.f / z;
        float r0 = fmaxf(a0 * rz + vb0, 0.f);
        float r1 = fmaxf(a1 * rz + vb1, 0.f);
        float4 acc;
        acc.x = r0 * w0.x + r1 * w1.x;
        acc.y = r0 * w0.y + r1 * w1.y;
        acc.z = r0 * w0.z + r1 * w1.z;
        acc.w = r0 * w0.w + r1 * w1.w;
        #pragma unroll
        for (int o = 16; o >= 1; o >>= 1) {
            acc.x += __shfl_xor_sync(FULLM, acc.x, o);
            acc.y += __shfl_xor_sync(FULLM, acc.y, o);
            acc.z += __shfl_xor_sync(FULLM, acc.z, o);
            acc.w += __shfl_xor_sync(FULLM, acc.w, o);
        }
        if (lane == 0) {
            g_n3[node].h   = acc;
            g_n3[node].asc = acc.x * as0 + acc.y * as1 + acc.z * as2 + acc.w * as3;
            g_adc3[node]   = acc.x * ad0 + acc.y * ad1 + acc.z * ad2 + acc.w * ad3;
        }
    }
}

// ===================== layer-3 aggregation + output ================

__global__ void __launch_bounds__(256) k_agg4(const float* __restrict__ bias,
                                              float4* __restrict__ out) {
    int t = threadIdx.x;
    int lane = t & 31, w = t >> 5;
    int warpsTotal = gridDim.x * 8;
    for (int node = blockIdx.x * 8 + w; node < NN; node += warpsTotal) {
        int beg = g_rowptr[node], end = g_rowptr[node + 1];
        float ad = g_adc3[node];
        float z = 0.f;
        float4 acc = make_float4(0.f, 0.f, 0.f, 0.f);
        #pragma unroll 4
        for (int i = beg + lane; i < end; i += 32) {
            int s = g_pk1[i].x;
            float4 hv = g_n3[s].h;            // same 32B sector as asc
            float e = g_n3[s].asc + ad;
            e = (e > 0.f) ? e : 0.2f * e;
            float ex = fast_exp(e);
            z += ex;
            acc.x = fmaf(ex, hv.x, acc.x);
            acc.y = fmaf(ex, hv.y, acc.y);
            acc.z = fmaf(ex, hv.z, acc.z);
            acc.w = fmaf(ex, hv.w, acc.w);
        }
        #pragma unroll
        for (int o = 16; o >= 1; o >>= 1) {
            z     += __shfl_xor_sync(FULLM, z, o);
            acc.x += __shfl_xor_sync(FULLM, acc.x, o);
            acc.y += __shfl_xor_sync(FULLM, acc.y, o);
            acc.z += __shfl_xor_sync(FULLM, acc.z, o);
            acc.w += __shfl_xor_sync(FULLM, acc.w, o);
        }
        if (lane == 0) {
            float4 o4;
            o4.x = 100.f / (1.f + __expf(-(acc.x / z + bias[0])));
            o4.y = 100.f / (1.f + __expf(-(acc.y / z + bias[1])));
            o4.z = 100.f / (1.f + __expf(-(acc.z / z + bias[2])));
            o4.w = 100.f / (1.f + __expf(-(acc.w / z + bias[3])));
            out[node] = o4;
        }
    }
}

// ============================== launch =============================

extern "C" void kernel_launch(void* const* d_in, const int* in_sizes, int n_in,
                              void* d_out, int out_size) {
    const float* x   = (const float*)d_in[0];
    const int*   ei  = (const int*)d_in[1];
    const float* W1  = (const float*)d_in[2];
    const float* a1s = (const float*)d_in[3];
    const float* a1d = (const float*)d_in[4];
    const float* b1  = (const float*)d_in[5];
    const float* W2  = (const float*)d_in[6];
    const float* a2s = (const float*)d_in[7];
    const float* a2d = (const float*)d_in[8];
    const float* b2  = (const float*)d_in[9];
    const float* W3  = (const float*)d_in[10];
    const float* a3s = (const float*)d_in[11];
    const float* a3d = (const float*)d_in[12];
    const float* b3  = (const float*)d_in[13];
    float4* out = (float4*)d_out;

    k_hist_gemm1<<<HB + AGG_GRID, 256>>>(ei, x, W1, a1s, a1d);
    k_scan<<<NB, 1024>>>();
    k_scatter_ex<<<(ETOT + 255) / 256, 256>>>(ei);
    k_aggmm2<<<AGG_GRID, 256>>>(b1, W2, a2s, a2d);     // profiled slot
    k_aggmm3<<<AGG_GRID, 256>>>(b2, W3, a3s, a3d);
    k_agg4<<<AGG_GRID, 256>>>(b3, out);
}